// round 3
// baseline (speedup 1.0000x reference)
#include <cuda_runtime.h>
#include <stdint.h>

#define N_POS 8192
#define N_NEG 4000
#define N_TOT (N_POS + N_POS * N_NEG)   // 32,776,192 (divisible by 4)
#define N_VEC (N_TOT / 4)               // 8,194,048

// Scratch (allocation-free rule: __device__ globals)
__device__ float          g_pos[N_POS];
__device__ unsigned short g_rowid[N_TOT];          // 65.55 MB
__device__ unsigned int   g_hist[N_POS / 2];       // packed: two u16 counters per word

// ---------------------------------------------------------------------------
// Pass 1: scan index once (int32! JAX silently downgrades int64->int32).
// Emit u16 row-id per element (0xFFFF = pos element), scatter the 8192 pos
// values, zero the global histogram.
// ---------------------------------------------------------------------------
__global__ void __launch_bounds__(256) mrr_pass1(
    const float* __restrict__ val, const int* __restrict__ idx)
{
    const unsigned int tid = blockIdx.x * blockDim.x + threadIdx.x;
    if (tid < N_POS / 2) g_hist[tid] = 0u;

    const unsigned int stride = gridDim.x * blockDim.x;
    const int4* __restrict__ idx4 = (const int4*)idx;
    ushort4* __restrict__ rid4 = (ushort4*)g_rowid;

    for (unsigned int v = tid; v < N_VEC; v += stride) {
        int4 q = idx4[v];
        unsigned int j0 = (unsigned int)q.x;
        unsigned int j1 = (unsigned int)q.y;
        unsigned int j2 = (unsigned int)q.z;
        unsigned int j3 = (unsigned int)q.w;
        unsigned int base = v * 4u;

        ushort4 r;
        if (j0 < N_POS) { r.x = 0xFFFFu; g_pos[j0] = val[base + 0]; }
        else            { r.x = (unsigned short)((j0 - N_POS) / (unsigned)N_NEG); }
        if (j1 < N_POS) { r.y = 0xFFFFu; g_pos[j1] = val[base + 1]; }
        else            { r.y = (unsigned short)((j1 - N_POS) / (unsigned)N_NEG); }
        if (j2 < N_POS) { r.z = 0xFFFFu; g_pos[j2] = val[base + 2]; }
        else            { r.z = (unsigned short)((j2 - N_POS) / (unsigned)N_NEG); }
        if (j3 < N_POS) { r.w = 0xFFFFu; g_pos[j3] = val[base + 3]; }
        else            { r.w = (unsigned short)((j3 - N_POS) / (unsigned)N_NEG); }

        rid4[v] = r;
    }
}

// ---------------------------------------------------------------------------
// Pass 2: SMEM-privatized histogram. pos table (32KB) + packed counters (16KB)
// = exactly 48KB static shared -> 4 blocks/SM. Counters are two u16 halves per
// u32 word; per-row total count <= 4000 so halves never overflow / carry.
// ---------------------------------------------------------------------------
__global__ void __launch_bounds__(512) mrr_pass2(const float* __restrict__ val)
{
    __shared__ float        s_pos[N_POS];      // 32768 B
    __shared__ unsigned int s_hist[N_POS / 2]; // 16384 B

    const int t = threadIdx.x;
    for (int i = t; i < N_POS; i += blockDim.x)     s_pos[i]  = g_pos[i];
    for (int i = t; i < N_POS / 2; i += blockDim.x) s_hist[i] = 0u;
    __syncthreads();

    const unsigned int tid = blockIdx.x * blockDim.x + t;
    const unsigned int stride = gridDim.x * blockDim.x;
    const float4*  __restrict__ v4 = (const float4*)val;
    const ushort4* __restrict__ r4 = (const ushort4*)g_rowid;

    for (unsigned int v = tid; v < N_VEC; v += stride) {
        float4  f = v4[v];
        ushort4 r = r4[v];
        if (r.x != 0xFFFFu && f.x > s_pos[r.x])
            atomicAdd(&s_hist[r.x >> 1], 1u << ((r.x & 1u) << 4));
        if (r.y != 0xFFFFu && f.y > s_pos[r.y])
            atomicAdd(&s_hist[r.y >> 1], 1u << ((r.y & 1u) << 4));
        if (r.z != 0xFFFFu && f.z > s_pos[r.z])
            atomicAdd(&s_hist[r.z >> 1], 1u << ((r.z & 1u) << 4));
        if (r.w != 0xFFFFu && f.w > s_pos[r.w])
            atomicAdd(&s_hist[r.w >> 1], 1u << ((r.w & 1u) << 4));
    }
    __syncthreads();

    // Flush packed words: whole-word add is safe (global per-row total <= 4000).
    for (int i = t; i < N_POS / 2; i += blockDim.x) {
        unsigned int h = s_hist[i];
        if (h) atomicAdd(&g_hist[i], h);
    }
}

// ---------------------------------------------------------------------------
// Pass 3: ranks -> sample_mrr, deterministic fixed-order mean.
// out[0] = mrr, out[1..8192] = sample_mrr
// ---------------------------------------------------------------------------
__global__ void __launch_bounds__(1024) mrr_pass3(float* __restrict__ out)
{
    __shared__ double ssum[1024];
    const int t = threadIdx.x;
    double local = 0.0;
    for (int r = t; r < N_POS; r += 1024) {
        unsigned int h = g_hist[r >> 1];
        unsigned int c = (r & 1) ? (h >> 16) : (h & 0xFFFFu);
        float s = 1.0f / (float)(1u + c);
        out[1 + r] = s;
        local += (double)s;
    }
    ssum[t] = local;
    __syncthreads();
    for (int off = 512; off > 0; off >>= 1) {
        if (t < off) ssum[t] += ssum[t + off];
        __syncthreads();
    }
    if (t == 0) out[0] = (float)(ssum[0] / (double)N_POS);
}

extern "C" void kernel_launch(void* const* d_in, const int* in_sizes, int n_in,
                              void* d_out, int out_size)
{
    const float* val = (const float*)d_in[0];
    const int*   idx = (const int*)d_in[1];
    float*       out = (float*)d_out;

    mrr_pass1<<<2048, 256>>>(val, idx);
    mrr_pass2<<<592, 512>>>(val);   // 148 SMs * 4 blocks (48KB smem each)
    mrr_pass3<<<1, 1024>>>(out);
}

// round 4
// speedup vs baseline: 1.0033x; 1.0033x over previous
#include <cuda_runtime.h>
#include <stdint.h>

#define N_POS 8192
#define N_NEG 4000
#define N_TOT (N_POS + N_POS * N_NEG)   // 32,776,192 (divisible by 4)
#define N_VEC (N_TOT / 4)               // 8,194,048

// Scratch (allocation-free rule: __device__ globals)
__device__ float          g_pos[N_POS];
__device__ unsigned short g_rowid[N_TOT];          // 65.55 MB
__device__ unsigned int   g_hist[N_POS / 2];       // packed: two u16 counters per word

// ---------------------------------------------------------------------------
// Pass 1: scan index once (int32 input). Emit u16 row-id per element
// (0xFFFF = pos element), scatter the 8192 pos values, zero the histogram.
// ---------------------------------------------------------------------------
__global__ void __launch_bounds__(256) mrr_pass1(
    const float* __restrict__ val, const int* __restrict__ idx)
{
    const unsigned int tid = blockIdx.x * blockDim.x + threadIdx.x;
    if (tid < N_POS / 2) g_hist[tid] = 0u;

    const unsigned int stride = gridDim.x * blockDim.x;
    const int4* __restrict__ idx4 = (const int4*)idx;
    ushort4* __restrict__ rid4 = (ushort4*)g_rowid;

    #pragma unroll 2
    for (unsigned int v = tid; v < N_VEC; v += stride) {
        int4 q = idx4[v];
        unsigned int j0 = (unsigned int)q.x;
        unsigned int j1 = (unsigned int)q.y;
        unsigned int j2 = (unsigned int)q.z;
        unsigned int j3 = (unsigned int)q.w;
        unsigned int base = v * 4u;

        ushort4 r;
        if (j0 < N_POS) { r.x = 0xFFFFu; g_pos[j0] = val[base + 0]; }
        else            { r.x = (unsigned short)((j0 - N_POS) / (unsigned)N_NEG); }
        if (j1 < N_POS) { r.y = 0xFFFFu; g_pos[j1] = val[base + 1]; }
        else            { r.y = (unsigned short)((j1 - N_POS) / (unsigned)N_NEG); }
        if (j2 < N_POS) { r.z = 0xFFFFu; g_pos[j2] = val[base + 2]; }
        else            { r.z = (unsigned short)((j2 - N_POS) / (unsigned)N_NEG); }
        if (j3 < N_POS) { r.w = 0xFFFFu; g_pos[j3] = val[base + 3]; }
        else            { r.w = (unsigned short)((j3 - N_POS) / (unsigned)N_NEG); }

        rid4[v] = r;
    }
}

// ---------------------------------------------------------------------------
// Pass 2: SMEM-privatized histogram with minority-side counting.
// For row r with pos value p:
//   p >  0 -> count (v >  p)   (expected fraction Phi(-p) < 0.5)
//   p <= 0 -> count (v <= p)
// inc = (v > p) XOR (p <= 0). Expected atomic fraction = E[min side] = 0.25.
// pos table (32KB) + packed u16x2 counters (16KB) = 48KB -> 4 blocks/SM.
// Per-row global count <= 4000 so u16 halves never overflow.
// ---------------------------------------------------------------------------
__global__ void __launch_bounds__(512) mrr_pass2(const float* __restrict__ val)
{
    __shared__ float        s_pos[N_POS];      // 32768 B
    __shared__ unsigned int s_hist[N_POS / 2]; // 16384 B

    const int t = threadIdx.x;
    for (int i = t; i < N_POS; i += blockDim.x)     s_pos[i]  = g_pos[i];
    for (int i = t; i < N_POS / 2; i += blockDim.x) s_hist[i] = 0u;
    __syncthreads();

    const unsigned int tid = blockIdx.x * blockDim.x + t;
    const unsigned int stride = gridDim.x * blockDim.x;
    const float4*  __restrict__ v4 = (const float4*)val;
    const ushort4* __restrict__ r4 = (const ushort4*)g_rowid;

    #pragma unroll 2
    for (unsigned int v = tid; v < N_VEC; v += stride) {
        float4  f = v4[v];
        ushort4 r = r4[v];
        {
            float p = s_pos[r.x & 0x1FFFu];
            if (r.x != 0xFFFFu && ((f.x > p) != (p <= 0.0f)))
                atomicAdd(&s_hist[r.x >> 1], 1u << ((r.x & 1u) << 4));
        }
        {
            float p = s_pos[r.y & 0x1FFFu];
            if (r.y != 0xFFFFu && ((f.y > p) != (p <= 0.0f)))
                atomicAdd(&s_hist[r.y >> 1], 1u << ((r.y & 1u) << 4));
        }
        {
            float p = s_pos[r.z & 0x1FFFu];
            if (r.z != 0xFFFFu && ((f.z > p) != (p <= 0.0f)))
                atomicAdd(&s_hist[r.z >> 1], 1u << ((r.z & 1u) << 4));
        }
        {
            float p = s_pos[r.w & 0x1FFFu];
            if (r.w != 0xFFFFu && ((f.w > p) != (p <= 0.0f)))
                atomicAdd(&s_hist[r.w >> 1], 1u << ((r.w & 1u) << 4));
        }
    }
    __syncthreads();

    // Flush packed words: whole-word add is safe (global per-row total <= 4000).
    for (int i = t; i < N_POS / 2; i += blockDim.x) {
        unsigned int h = s_hist[i];
        if (h) atomicAdd(&g_hist[i], h);
    }
}

// ---------------------------------------------------------------------------
// Pass 3: undo minority-side flip, ranks -> sample_mrr, deterministic mean.
// out[0] = mrr, out[1..8192] = sample_mrr
// ---------------------------------------------------------------------------
__global__ void __launch_bounds__(1024) mrr_pass3(float* __restrict__ out)
{
    __shared__ double ssum[1024];
    const int t = threadIdx.x;
    double local = 0.0;
    for (int r = t; r < N_POS; r += 1024) {
        unsigned int h = g_hist[r >> 1];
        unsigned int c = (r & 1) ? (h >> 16) : (h & 0xFFFFu);
        float p = g_pos[r];
        unsigned int cnt_gt = (p > 0.0f) ? c : ((unsigned)N_NEG - c);
        float s = 1.0f / (float)(1u + cnt_gt);
        out[1 + r] = s;
        local += (double)s;
    }
    ssum[t] = local;
    __syncthreads();
    for (int off = 512; off > 0; off >>= 1) {
        if (t < off) ssum[t] += ssum[t + off];
        __syncthreads();
    }
    if (t == 0) out[0] = (float)(ssum[0] / (double)N_POS);
}

extern "C" void kernel_launch(void* const* d_in, const int* in_sizes, int n_in,
                              void* d_out, int out_size)
{
    const float* val = (const float*)d_in[0];
    const int*   idx = (const int*)d_in[1];
    float*       out = (float*)d_out;

    mrr_pass1<<<2048, 256>>>(val, idx);
    mrr_pass2<<<592, 512>>>(val);   // 148 SMs * 4 blocks (48KB smem each)
    mrr_pass3<<<1, 1024>>>(out);
}